// round 13
// baseline (speedup 1.0000x reference)
#include <cuda_runtime.h>
#include <cuda_bf16.h>
#include <math.h>
#include <stdint.h>

#define BATCH   2048
#define IN_DIM  376
#define HID     1024
#define NOUT    17
#define NCELLS  6
#define NOPS    5
#define KP0     384            // IN_DIM padded to multiple of BK

#define BM 128
#define BN 64
#define BK 32
#define NTHREADS 256

// smem (u32 units): per buffer: A 2 planes x 128 rows x 20, B 8 (op,plane) x 64 x 20
#define A_ROW_STRIDE 20
#define A_PLANE      (128 * A_ROW_STRIDE)          // 2560 u32
#define B_TILE       (64 * A_ROW_STRIDE)           // 1280 u32
#define BUF_U32      (2 * A_PLANE + 8 * B_TILE)    // 15360 u32 = 60 KB
#define OFF_B_U32    (2 * A_PLANE)
#define BUF_BYTES    (BUF_U32 * 4)
#define SMEM_BYTES   (2 * BUF_U32 * 4)             // 120 KB

// ---------------------------------------------------------------------------
// device scratch
// ---------------------------------------------------------------------------
__device__ float g_acc[5u * BATCH * HID];
__device__ float g_z[150];
// pre-split, transposed weights: [pair][n][k] bf16, k contiguous
__device__ __nv_bfloat16 g_wt0_hi[20u * HID * KP0];
__device__ __nv_bfloat16 g_wt0_lo[20u * HID * KP0];
__device__ __nv_bfloat16 g_wth_hi[40u * HID * HID];
__device__ __nv_bfloat16 g_wth_lo[40u * HID * HID];
// pre-split activations: x planes + node 1..4 planes ([m][k], k contiguous)
__device__ __nv_bfloat16 g_x_hi[(size_t)BATCH * KP0];
__device__ __nv_bfloat16 g_x_lo[(size_t)BATCH * KP0];
__device__ __nv_bfloat16 g_a_hi[4u * BATCH * HID];
__device__ __nv_bfloat16 g_a_lo[4u * BATCH * HID];

// ---------------------------------------------------------------------------
__device__ __forceinline__ void bf16split(float a, __nv_bfloat16& hi, __nv_bfloat16& lo) {
    hi = __float2bfloat16_rn(a);
    lo = __float2bfloat16_rn(a - __bfloat162float(hi));
}
__device__ __forceinline__ uint32_t packbf2(__nv_bfloat16 a, __nv_bfloat16 b) {
    __nv_bfloat162 v(a, b);
    return *reinterpret_cast<uint32_t*>(&v);
}
__device__ __forceinline__ uint32_t smem_u32(const void* p) {
    uint32_t a;
    asm("{ .reg .u64 t; cvta.to.shared.u64 t, %1; cvt.u32.u64 %0, t; }"
        : "=r"(a) : "l"(p));
    return a;
}
__device__ __forceinline__ void ldmx4(uint32_t* r, uint32_t addr) {
    asm volatile("ldmatrix.sync.aligned.m8n8.x4.shared.b16 {%0,%1,%2,%3}, [%4];"
        : "=r"(r[0]), "=r"(r[1]), "=r"(r[2]), "=r"(r[3]) : "r"(addr));
}
__device__ __forceinline__ void cp16(uint32_t dst, const void* src) {
    asm volatile("cp.async.cg.shared.global [%0], [%1], 16;" :: "r"(dst), "l"(src));
}
__device__ __forceinline__ void cp_commit() { asm volatile("cp.async.commit_group;"); }
__device__ __forceinline__ void cp_wait0()  { asm volatile("cp.async.wait_group 0;" ::: "memory"); }

__device__ __forceinline__ void mma16816(float* d, const uint32_t* a,
                                         uint32_t b0, uint32_t b1) {
    asm volatile(
        "mma.sync.aligned.m16n8k16.row.col.f32.bf16.bf16.f32 "
        "{%0,%1,%2,%3}, {%4,%5,%6,%7}, {%8,%9}, {%0,%1,%2,%3};\n"
        : "+f"(d[0]), "+f"(d[1]), "+f"(d[2]), "+f"(d[3])
        : "r"(a[0]), "r"(a[1]), "r"(a[2]), "r"(a[3]), "r"(b0), "r"(b1));
}

// ---------------------------------------------------------------------------
// z = softmax(log_alphas + eps) over op axis (TAU = 1)
// ---------------------------------------------------------------------------
__global__ void z_kernel(const float* __restrict__ la, const float* __restrict__ eps) {
    int t = threadIdx.x;
    if (t < 30) {
        float v[NOPS], mx = -1e30f;
        #pragma unroll
        for (int o = 0; o < NOPS; o++) { v[o] = la[t*NOPS+o] + eps[t*NOPS+o]; mx = fmaxf(mx, v[o]); }
        float s = 0.f;
        #pragma unroll
        for (int o = 0; o < NOPS; o++) { v[o] = expf(v[o] - mx); s += v[o]; }
        float inv = 1.f / s;
        #pragma unroll
        for (int o = 0; o < NOPS; o++) g_z[t*NOPS+o] = v[o] * inv;
    }
}

// ---------------------------------------------------------------------------
// Pre-pass: split x into bf16 hi/lo planes ([m][KP0], zero-padded)
// ---------------------------------------------------------------------------
__global__ void split_x_kernel(const float* __restrict__ x) {
    const int k = blockIdx.x * 128 + threadIdx.x;
    const int m = blockIdx.y;
    if (k >= KP0) return;
    float v = (k < IN_DIM) ? x[(size_t)m * IN_DIM + k] : 0.f;
    __nv_bfloat16 hi, lo; bf16split(v, hi, lo);
    g_x_hi[(size_t)m * KP0 + k] = hi;
    g_x_lo[(size_t)m * KP0 + k] = lo;
}

// ---------------------------------------------------------------------------
// Pre-pass: transpose + bf16-split weights into [pair][n][k] (k contiguous)
// ---------------------------------------------------------------------------
__global__ void split_t0_kernel(const float* __restrict__ W0) {
    __shared__ float t[32][33];
    const int pair = blockIdx.z;            // (i-1)*4 + op
    const int i = (pair >> 2) + 1, op = pair & 3;
    const float* src = W0 + ((size_t)(i * NOPS + op)) * IN_DIM * HID;
    const int kb = blockIdx.x * 32, nb = blockIdx.y * 32;
    const int tx = threadIdx.x, ty = threadIdx.y;       // (32, 8)
    #pragma unroll
    for (int r = 0; r < 4; r++) {
        int k = kb + ty * 4 + r;
        t[ty*4+r][tx] = (k < IN_DIM) ? src[(size_t)k * HID + nb + tx] : 0.f;
    }
    __syncthreads();
    __nv_bfloat16* dh = g_wt0_hi + (size_t)pair * HID * KP0;
    __nv_bfloat16* dl = g_wt0_lo + (size_t)pair * HID * KP0;
    #pragma unroll
    for (int r = 0; r < 4; r++) {
        int n = nb + ty * 4 + r, k = kb + tx;
        __nv_bfloat16 hi, lo; bf16split(t[tx][ty*4+r], hi, lo);
        dh[(size_t)n * KP0 + k] = hi;
        dl[(size_t)n * KP0 + k] = lo;
    }
}

__global__ void split_th_kernel(const float* __restrict__ Wh) {
    __shared__ float t[32][33];
    const int pair = blockIdx.z;            // e*4 + op
    const int e = pair >> 2, op = pair & 3;
    int s, i;
    if      (e < 4) { s = 1; i = e + 2; }
    else if (e < 7) { s = 2; i = e - 4 + 3; }
    else if (e < 9) { s = 3; i = e - 7 + 4; }
    else            { s = 4; i = 5; }
    const float* src = Wh + ((size_t)(((s-1) * NCELLS + i) * NOPS + op)) * HID * HID;
    const int kb = blockIdx.x * 32, nb = blockIdx.y * 32;
    const int tx = threadIdx.x, ty = threadIdx.y;
    #pragma unroll
    for (int r = 0; r < 4; r++)
        t[ty*4+r][tx] = src[(size_t)(kb + ty*4 + r) * HID + nb + tx];
    __syncthreads();
    __nv_bfloat16* dh = g_wth_hi + (size_t)pair * HID * HID;
    __nv_bfloat16* dl = g_wth_lo + (size_t)pair * HID * HID;
    #pragma unroll
    for (int r = 0; r < 4; r++) {
        int n = nb + ty * 4 + r, k = kb + tx;
        __nv_bfloat16 hi, lo; bf16split(t[tx][ty*4+r], hi, lo);
        dh[(size_t)n * HID + k] = hi;
        dl[(size_t)n * HID + k] = lo;
    }
}

// ---------------------------------------------------------------------------
// Stage GEMM: bf16x3 mma.sync; A and B via cp.async (pre-split planes).
// CTA = [128 x 64] x 4 ops; 8 warps, warp tile 32x32 (grid 4m x 2n) —
// cuts smem read traffic ~20% vs 32x16 warps. KP compile-time.
// grid = (BATCH/BM, HID/BN, 5-stage)
// ---------------------------------------------------------------------------
template<int KP>
__global__ __launch_bounds__(NTHREADS)
void stage_mma_kernel(int stage, const float* __restrict__ b0,
                      const float* __restrict__ bh)
{
    extern __shared__ uint32_t smem[];
    const uint32_t sbase = smem_u32(smem);
    const int tid = threadIdx.x;
    const int i   = stage + 1 + blockIdx.z;
    const int bm0 = blockIdx.x * BM;
    const int bn0 = blockIdx.y * BN;

    const __nv_bfloat16 *Ahi, *Alo, *Bhi, *Blo;
    const float* bias;
    if (stage == 0) {
        Ahi = g_x_hi; Alo = g_x_lo;
        const size_t pb = (size_t)((i - 1) * 4) * HID * KP;
        Bhi = g_wt0_hi + pb; Blo = g_wt0_lo + pb;
        bias = b0 + (size_t)(i * NOPS) * HID;
    } else {
        Ahi = g_a_hi + (size_t)(stage - 1) * BATCH * HID;
        Alo = g_a_lo + (size_t)(stage - 1) * BATCH * HID;
        static const int eoff[5] = {0, 0, 4, 7, 9};
        const int e = eoff[stage] + (i - stage - 1);
        const size_t pb = (size_t)(e * 4) * HID * KP;
        Bhi = g_wth_hi + pb; Blo = g_wth_lo + pb;
        bias = bh + (size_t)(((stage - 1) * NCELLS + i) * NOPS) * HID;
    }
    float* accOut = g_acc + (size_t)(i - 1) * BATCH * HID;
    const float* zp = g_z + (stage * NCELLS + i) * NOPS;

    const int w    = tid >> 5, lane = tid & 31;
    const int wm   = (w & 3) * 32;          // warp M offset (4 m-groups)
    const int wn   = (w >> 2) * 32;         // warp N offset (2 n-groups)
    const int qr   = lane >> 2;             // t/4
    const int qk   = lane & 3;              // t%4
    const int lg   = lane >> 3;             // ldmatrix group 0..3
    const int lr   = lane & 7;              // ldmatrix row in group

    // ldmatrix per-lane byte offsets (within a plane/tile)
    const uint32_t aoff = ((wm + (lg & 1) * 8 + lr) * A_ROW_STRIDE + (lg >> 1) * 4) * 4;
    const uint32_t boff = ((wn + (lg >> 1) * 8 + lr) * A_ROW_STRIDE + (lg & 1) * 4) * 4;

    // ---- register-thin producer mappings ----
    // A: thread owns (row0 = (tid>>2)&63, ch = tid&3); 4 chunks: plane x {row0, row0+64}
    // B: thread owns (n-row = (tid>>2)&63, ch); 8 chunks: (op 0..3) x (hi,lo)
    const int ch    = tid & 3;
    const int arow0 = (tid >> 2) & 63;

    const __nv_bfloat16* aP0 = Ahi + (size_t)(bm0 + arow0) * KP + ch * 8;   // plane hi
    const __nv_bfloat16* aP1 = Alo + (size_t)(bm0 + arow0) * KP + ch * 8;   // plane lo
    const __nv_bfloat16* bPh = Bhi + (size_t)(bn0 + arow0) * KP + ch * 8;
    const __nv_bfloat16* bPl = Blo + (size_t)(bn0 + arow0) * KP + ch * 8;

    const uint32_t aD = sbase + (arow0 * A_ROW_STRIDE + ch * 4) * 4;
    const uint32_t bD = sbase + (OFF_B_U32 + arow0 * A_ROW_STRIDE + ch * 4) * 4;

    #define CP_TILE(db)                                                          \
        do {                                                                     \
            cp16(aD + (db), aP0);                                                \
            cp16(aD + (db) + 64 * A_ROW_STRIDE * 4, aP0 + (size_t)64 * KP);      \
            cp16(aD + (db) + A_PLANE * 4, aP1);                                  \
            cp16(aD + (db) + A_PLANE * 4 + 64 * A_ROW_STRIDE * 4,                \
                 aP1 + (size_t)64 * KP);                                         \
            cp16(bD + (db) + 0 * B_TILE * 4, bPh + (size_t)0 * HID * KP);        \
            cp16(bD + (db) + 1 * B_TILE * 4, bPl + (size_t)0 * HID * KP);        \
            cp16(bD + (db) + 2 * B_TILE * 4, bPh + (size_t)1 * HID * KP);        \
            cp16(bD + (db) + 3 * B_TILE * 4, bPl + (size_t)1 * HID * KP);        \
            cp16(bD + (db) + 4 * B_TILE * 4, bPh + (size_t)2 * HID * KP);        \
            cp16(bD + (db) + 5 * B_TILE * 4, bPl + (size_t)2 * HID * KP);        \
            cp16(bD + (db) + 6 * B_TILE * 4, bPh + (size_t)3 * HID * KP);        \
            cp16(bD + (db) + 7 * B_TILE * 4, bPl + (size_t)3 * HID * KP);        \
        } while (0)

    float acc[4][2][4][4];                  // [op][mf][nf][c]
    #pragma unroll
    for (int o = 0; o < 4; o++)
        #pragma unroll
        for (int mf = 0; mf < 2; mf++)
            #pragma unroll
            for (int nf = 0; nf < 4; nf++)
                #pragma unroll
                for (int c = 0; c < 4; c++) acc[o][mf][nf][c] = 0.f;

    constexpr int nk = KP / BK;

    // prologue: fill buffer 0
    CP_TILE(0);
    cp_commit();
    cp_wait0();
    __syncthreads();

    #pragma unroll 1
    for (int kt = 0; kt < nk; kt++) {
        const int cur  = kt & 1;
        const bool more = (kt + 1 < nk);
        if (more) {
            aP0 += BK; aP1 += BK; bPh += BK; bPl += BK;
            CP_TILE((cur ^ 1) * BUF_BYTES);
            cp_commit();
        }

        const uint32_t bufA = sbase + cur * BUF_BYTES;
        const uint32_t bufB = bufA + OFF_B_U32 * 4;
        #pragma unroll
        for (int kp = 0; kp < 2; kp++) {
            uint32_t afr[2][2][4];    // [plane][mf][a0..a3]
            #pragma unroll
            for (int pl = 0; pl < 2; pl++)
                #pragma unroll
                for (int mf = 0; mf < 2; mf++)
                    ldmx4(afr[pl][mf],
                          bufA + pl * (A_PLANE * 4) + aoff + mf * (16 * A_ROW_STRIDE * 4) + kp * 32);
            #pragma unroll
            for (int op = 0; op < 4; op++) {
                uint32_t bfrg[2][2][4];   // [plane][nhalf][nf0b0, nf0b1, nf1b0, nf1b1]
                #pragma unroll
                for (int pl = 0; pl < 2; pl++)
                    #pragma unroll
                    for (int nh = 0; nh < 2; nh++)
                        ldmx4(bfrg[pl][nh],
                              bufB + (op * 2 + pl) * (B_TILE * 4) + boff
                                   + nh * (16 * A_ROW_STRIDE * 4) + kp * 32);
                #pragma unroll
                for (int mf = 0; mf < 2; mf++)
                    #pragma unroll
                    for (int nf = 0; nf < 4; nf++) {
                        float* d = acc[op][mf][nf];
                        const int nh = nf >> 1, nq = (nf & 1) * 2;
                        mma16816(d, afr[0][mf], bfrg[0][nh][nq], bfrg[0][nh][nq+1]); // hi*hi
                        mma16816(d, afr[0][mf], bfrg[1][nh][nq], bfrg[1][nh][nq+1]); // hi*lo
                        mma16816(d, afr[1][mf], bfrg[0][nh][nq], bfrg[0][nh][nq+1]); // lo*hi
                    }
            }
        }
        if (more) {
            cp_wait0();
            __syncthreads();
        }
    }
    #undef CP_TILE

    // ---- epilogue: bias + act + z-weighted op-sum, RMW into g_acc; when this
    //      stage finalizes node i == stage+1 (<=4), also emit bf16 split planes.
    const float z0 = zp[0], z1 = zp[1], z2 = zp[2], z3 = zp[3];
    const bool emit_split = (i == stage + 1) && (i <= 4);
    uint32_t* sp_hi = (uint32_t*)(g_a_hi + (size_t)(i - 1) * BATCH * HID);
    uint32_t* sp_lo = (uint32_t*)(g_a_lo + (size_t)(i - 1) * BATCH * HID);

    #pragma unroll
    for (int mf = 0; mf < 2; mf++)
        #pragma unroll
        for (int nf = 0; nf < 4; nf++) {
            const int n0 = bn0 + wn + nf * 8 + qk * 2;
            float bv[4][2];
            #pragma unroll
            for (int op = 0; op < 4; op++) {
                bv[op][0] = bias[op * HID + n0];
                bv[op][1] = bias[op * HID + n0 + 1];
            }
            #pragma unroll
            for (int half = 0; half < 2; half++) {
                const int m = bm0 + wm + mf * 16 + qr + half * 8;
                float r0 = 0.f, r1 = 0.f;
                #pragma unroll
                for (int op = 0; op < 4; op++) {
                    const float p0 = acc[op][mf][nf][half * 2 + 0] + bv[op][0];
                    const float p1 = acc[op][mf][nf][half * 2 + 1] + bv[op][1];
                    float a0, a1;
                    switch (op) {
                        case 0:  a0 = tanhf(p0);                      a1 = tanhf(p1);                      break;
                        case 1:  a0 = fmaxf(p0, 0.f);                 a1 = fmaxf(p1, 0.f);                 break;
                        case 2:  a0 = p0 > 0.f ? p0 : expm1f(p0);     a1 = p1 > 0.f ? p1 : expm1f(p1);     break;
                        default: a0 = p0 > 0.f ? p0 : 0.01f * p0;     a1 = p1 > 0.f ? p1 : 0.01f * p1;     break;
                    }
                    const float zv = (op == 0) ? z0 : (op == 1) ? z1 : (op == 2) ? z2 : z3;
                    r0 += zv * a0; r1 += zv * a1;
                }
                float* dst = accOut + (size_t)m * HID + n0;
                if (stage != 0) {
                    float2 old = *reinterpret_cast<const float2*>(dst);
                    r0 += old.x; r1 += old.y;
                }
                float2 res; res.x = r0; res.y = r1;
                *reinterpret_cast<float2*>(dst) = res;
                if (emit_split) {
                    __nv_bfloat16 h0, l0, h1, l1;
                    bf16split(r0, h0, l0);
                    bf16split(r1, h1, l1);
                    const size_t widx = ((size_t)m * HID + n0) >> 1;
                    sp_hi[widx] = packbf2(h0, h1);
                    sp_lo[widx] = packbf2(l0, l1);
                }
            }
        }
}

// ---------------------------------------------------------------------------
// out = tanh(acc5 @ Wout + bout)
// ---------------------------------------------------------------------------
__global__ void out_kernel(const float* __restrict__ Wout,
                           const float* __restrict__ bout,
                           float* __restrict__ out)
{
    const int gw   = (blockIdx.x * blockDim.x + threadIdx.x) >> 5;
    const int lane = threadIdx.x & 31;
    if (gw >= BATCH) return;
    const float* a = g_acc + (size_t)4 * BATCH * HID + (size_t)gw * HID;

    float s[NOUT];
    #pragma unroll
    for (int n = 0; n < NOUT; n++) s[n] = 0.f;
    for (int kk = lane; kk < HID; kk += 32) {
        const float av = a[kk];
        const float* wr = Wout + (size_t)kk * NOUT;
        #pragma unroll
        for (int n = 0; n < NOUT; n++) s[n] = fmaf(av, wr[n], s[n]);
    }
    #pragma unroll
    for (int off = 16; off; off >>= 1)
        #pragma unroll
        for (int n = 0; n < NOUT; n++)
            s[n] += __shfl_down_sync(0xffffffffu, s[n], off);
    if (lane == 0) {
        #pragma unroll
        for (int n = 0; n < NOUT; n++)
            out[(size_t)gw * NOUT + n] = tanhf(s[n] + bout[n]);
    }
}

// ---------------------------------------------------------------------------
extern "C" void kernel_launch(void* const* d_in, const int* in_sizes, int n_in,
                              void* d_out, int out_size)
{
    const float* x    = (const float*)d_in[0];
    const float* W0   = (const float*)d_in[1];
    const float* b0   = (const float*)d_in[2];
    const float* Wh   = (const float*)d_in[3];
    const float* bh   = (const float*)d_in[4];
    const float* Wout = (const float*)d_in[5];
    const float* bout = (const float*)d_in[6];
    const float* la   = (const float*)d_in[7];
    const float* eps  = (const float*)d_in[8];
    float* out = (float*)d_out;

    cudaFuncSetAttribute(stage_mma_kernel<KP0>,
                         cudaFuncAttributeMaxDynamicSharedMemorySize, SMEM_BYTES);
    cudaFuncSetAttribute(stage_mma_kernel<HID>,
                         cudaFuncAttributeMaxDynamicSharedMemorySize, SMEM_BYTES);

    z_kernel<<<1, 32>>>(la, eps);
    split_x_kernel<<<dim3(KP0 / 128, BATCH), 128>>>(x);
    split_t0_kernel<<<dim3(KP0 / 32, HID / 32, 20), dim3(32, 8)>>>(W0);
    split_th_kernel<<<dim3(HID / 32, HID / 32, 40), dim3(32, 8)>>>(Wh);
    for (int k = 0; k < 5; k++) {
        dim3 grid(BATCH / BM, HID / BN, 5 - k);
        if (k == 0)
            stage_mma_kernel<KP0><<<grid, NTHREADS, SMEM_BYTES>>>(k, b0, bh);
        else
            stage_mma_kernel<HID><<<grid, NTHREADS, SMEM_BYTES>>>(k, b0, bh);
    }
    out_kernel<<<(BATCH * 32) / 256, 256>>>(Wout, bout, out);
}

// round 14
// speedup vs baseline: 1.2032x; 1.2032x over previous
#include <cuda_runtime.h>
#include <cuda_bf16.h>
#include <math.h>
#include <stdint.h>

#define BATCH   2048
#define IN_DIM  376
#define HID     1024
#define NOUT    17
#define NCELLS  6
#define NOPS    5
#define KP0     384            // IN_DIM padded to multiple of BK

#define BM 128
#define BN 32
#define BK 32
#define NTHREADS 256

// smem (u32 units): per buffer: A 2 planes x 128 rows x 20, B 8 (op,plane) x 32 x 20
#define A_ROW_STRIDE 20
#define A_PLANE      (128 * A_ROW_STRIDE)          // 2560 u32
#define B_TILE       (32 * A_ROW_STRIDE)           // 640 u32
#define BUF_U32      (2 * A_PLANE + 8 * B_TILE)    // 10240 u32 = 40 KB
#define OFF_B_U32    (2 * A_PLANE)
#define BUF_BYTES    (BUF_U32 * 4)
#define SMEM_BYTES   (2 * BUF_U32 * 4)             // 80 KB

// ---------------------------------------------------------------------------
// device scratch
// ---------------------------------------------------------------------------
__device__ float g_acc[5u * BATCH * HID];
__device__ float g_z[150];
// pre-split, transposed weights: [pair][n][k] bf16, k contiguous
__device__ __nv_bfloat16 g_wt0_hi[20u * HID * KP0];
__device__ __nv_bfloat16 g_wt0_lo[20u * HID * KP0];
__device__ __nv_bfloat16 g_wth_hi[40u * HID * HID];
__device__ __nv_bfloat16 g_wth_lo[40u * HID * HID];
// pre-split activations: x planes + node 1..4 planes ([m][k], k contiguous)
__device__ __nv_bfloat16 g_x_hi[(size_t)BATCH * KP0];
__device__ __nv_bfloat16 g_x_lo[(size_t)BATCH * KP0];
__device__ __nv_bfloat16 g_a_hi[4u * BATCH * HID];
__device__ __nv_bfloat16 g_a_lo[4u * BATCH * HID];

// ---------------------------------------------------------------------------
__device__ __forceinline__ void bf16split(float a, __nv_bfloat16& hi, __nv_bfloat16& lo) {
    hi = __float2bfloat16_rn(a);
    lo = __float2bfloat16_rn(a - __bfloat162float(hi));
}
__device__ __forceinline__ uint32_t packbf2(__nv_bfloat16 a, __nv_bfloat16 b) {
    __nv_bfloat162 v(a, b);
    return *reinterpret_cast<uint32_t*>(&v);
}
__device__ __forceinline__ uint32_t smem_u32(const void* p) {
    uint32_t a;
    asm("{ .reg .u64 t; cvta.to.shared.u64 t, %1; cvt.u32.u64 %0, t; }"
        : "=r"(a) : "l"(p));
    return a;
}
__device__ __forceinline__ void ldmx4(uint32_t* r, uint32_t addr) {
    asm volatile("ldmatrix.sync.aligned.m8n8.x4.shared.b16 {%0,%1,%2,%3}, [%4];"
        : "=r"(r[0]), "=r"(r[1]), "=r"(r[2]), "=r"(r[3]) : "r"(addr));
}
__device__ __forceinline__ void cp16(uint32_t dst, const void* src) {
    asm volatile("cp.async.cg.shared.global [%0], [%1], 16;" :: "r"(dst), "l"(src));
}
__device__ __forceinline__ void cp_commit() { asm volatile("cp.async.commit_group;"); }
__device__ __forceinline__ void cp_wait0()  { asm volatile("cp.async.wait_group 0;" ::: "memory"); }

__device__ __forceinline__ void mma16816(float* d, const uint32_t* a,
                                         uint32_t b0, uint32_t b1) {
    asm volatile(
        "mma.sync.aligned.m16n8k16.row.col.f32.bf16.bf16.f32 "
        "{%0,%1,%2,%3}, {%4,%5,%6,%7}, {%8,%9}, {%0,%1,%2,%3};\n"
        : "+f"(d[0]), "+f"(d[1]), "+f"(d[2]), "+f"(d[3])
        : "r"(a[0]), "r"(a[1]), "r"(a[2]), "r"(a[3]), "r"(b0), "r"(b1));
}

// ---------------------------------------------------------------------------
// z = softmax(log_alphas + eps) over op axis (TAU = 1)
// ---------------------------------------------------------------------------
__global__ void z_kernel(const float* __restrict__ la, const float* __restrict__ eps) {
    int t = threadIdx.x;
    if (t < 30) {
        float v[NOPS], mx = -1e30f;
        #pragma unroll
        for (int o = 0; o < NOPS; o++) { v[o] = la[t*NOPS+o] + eps[t*NOPS+o]; mx = fmaxf(mx, v[o]); }
        float s = 0.f;
        #pragma unroll
        for (int o = 0; o < NOPS; o++) { v[o] = expf(v[o] - mx); s += v[o]; }
        float inv = 1.f / s;
        #pragma unroll
        for (int o = 0; o < NOPS; o++) g_z[t*NOPS+o] = v[o] * inv;
    }
}

// ---------------------------------------------------------------------------
// Pre-pass: split x into bf16 hi/lo planes ([m][KP0], zero-padded)
// ---------------------------------------------------------------------------
__global__ void split_x_kernel(const float* __restrict__ x) {
    const int k = blockIdx.x * 128 + threadIdx.x;
    const int m = blockIdx.y;
    if (k >= KP0) return;
    float v = (k < IN_DIM) ? x[(size_t)m * IN_DIM + k] : 0.f;
    __nv_bfloat16 hi, lo; bf16split(v, hi, lo);
    g_x_hi[(size_t)m * KP0 + k] = hi;
    g_x_lo[(size_t)m * KP0 + k] = lo;
}

// ---------------------------------------------------------------------------
// Pre-pass: transpose + bf16-split weights into [pair][n][k] (k contiguous),
// packed bf16x2 stores (64k x 32n tiles).
// ---------------------------------------------------------------------------
__global__ void split_t0_kernel(const float* __restrict__ W0) {
    __shared__ float t[64][33];
    const int pair = blockIdx.z;            // (i-1)*4 + op
    const int i = (pair >> 2) + 1, op = pair & 3;
    const float* src = W0 + ((size_t)(i * NOPS + op)) * IN_DIM * HID;
    const int kb = blockIdx.x * 64, nb = blockIdx.y * 32;
    const int tx = threadIdx.x, ty = threadIdx.y;       // (32, 8)
    #pragma unroll
    for (int r = 0; r < 8; r++) {
        int k = ty * 8 + r;                 // 0..63
        t[k][tx] = (kb + k < IN_DIM) ? src[(size_t)(kb + k) * HID + nb + tx] : 0.f;
    }
    __syncthreads();
    uint32_t* dh = (uint32_t*)(g_wt0_hi + (size_t)pair * HID * KP0);
    uint32_t* dl = (uint32_t*)(g_wt0_lo + (size_t)pair * HID * KP0);
    #pragma unroll
    for (int r = 0; r < 4; r++) {
        const int n = ty * 4 + r;           // 0..31
        __nv_bfloat16 h0, l0, h1, l1;
        bf16split(t[tx * 2][n], h0, l0);
        bf16split(t[tx * 2 + 1][n], h1, l1);
        const size_t w = ((size_t)(nb + n) * KP0 + kb) / 2 + tx;
        dh[w] = packbf2(h0, h1);
        dl[w] = packbf2(l0, l1);
    }
}

__global__ void split_th_kernel(const float* __restrict__ Wh) {
    __shared__ float t[64][33];
    const int pair = blockIdx.z;            // e*4 + op
    const int e = pair >> 2, op = pair & 3;
    int s, i;
    if      (e < 4) { s = 1; i = e + 2; }
    else if (e < 7) { s = 2; i = e - 4 + 3; }
    else if (e < 9) { s = 3; i = e - 7 + 4; }
    else            { s = 4; i = 5; }
    const float* src = Wh + ((size_t)(((s-1) * NCELLS + i) * NOPS + op)) * HID * HID;
    const int kb = blockIdx.x * 64, nb = blockIdx.y * 32;
    const int tx = threadIdx.x, ty = threadIdx.y;       // (32, 8)
    #pragma unroll
    for (int r = 0; r < 8; r++) {
        int k = ty * 8 + r;
        t[k][tx] = src[(size_t)(kb + k) * HID + nb + tx];
    }
    __syncthreads();
    uint32_t* dh = (uint32_t*)(g_wth_hi + (size_t)pair * HID * HID);
    uint32_t* dl = (uint32_t*)(g_wth_lo + (size_t)pair * HID * HID);
    #pragma unroll
    for (int r = 0; r < 4; r++) {
        const int n = ty * 4 + r;
        __nv_bfloat16 h0, l0, h1, l1;
        bf16split(t[tx * 2][n], h0, l0);
        bf16split(t[tx * 2 + 1][n], h1, l1);
        const size_t w = ((size_t)(nb + n) * HID + kb) / 2 + tx;
        dh[w] = packbf2(h0, h1);
        dl[w] = packbf2(l0, l1);
    }
}

// ---------------------------------------------------------------------------
// Stage GEMM: bf16x3 mma.sync; A and B both via cp.async (pre-split planes).
// KP compile-time; producers register-thin. CTA = [128 x 32] x 4 ops;
// warp = 32x16; 2 CTAs/SM. grid = (BATCH/BM, HID/BN, 5-stage)
// ---------------------------------------------------------------------------
template<int KP>
__global__ __launch_bounds__(NTHREADS, 2)
void stage_mma_kernel(int stage, const float* __restrict__ b0,
                      const float* __restrict__ bh)
{
    extern __shared__ uint32_t smem[];
    const uint32_t sbase = smem_u32(smem);
    const int tid = threadIdx.x;
    const int i   = stage + 1 + blockIdx.z;
    const int bm0 = blockIdx.x * BM;
    const int bn0 = blockIdx.y * BN;

    const __nv_bfloat16 *Ahi, *Alo, *Bhi, *Blo;
    const float* bias;
    if (stage == 0) {
        Ahi = g_x_hi; Alo = g_x_lo;
        const size_t pb = (size_t)((i - 1) * 4) * HID * KP;
        Bhi = g_wt0_hi + pb; Blo = g_wt0_lo + pb;
        bias = b0 + (size_t)(i * NOPS) * HID;
    } else {
        Ahi = g_a_hi + (size_t)(stage - 1) * BATCH * HID;
        Alo = g_a_lo + (size_t)(stage - 1) * BATCH * HID;
        static const int eoff[5] = {0, 0, 4, 7, 9};
        const int e = eoff[stage] + (i - stage - 1);
        const size_t pb = (size_t)(e * 4) * HID * KP;
        Bhi = g_wth_hi + pb; Blo = g_wth_lo + pb;
        bias = bh + (size_t)(((stage - 1) * NCELLS + i) * NOPS) * HID;
    }
    float* accOut = g_acc + (size_t)(i - 1) * BATCH * HID;
    const float* zp = g_z + (stage * NCELLS + i) * NOPS;

    const int w    = tid >> 5, lane = tid & 31;
    const int wm   = (w & 3) * 32;          // warp M offset
    const int wn   = (w >> 2) * 16;         // warp N offset
    const int qr   = lane >> 2;             // t/4
    const int qk   = lane & 3;              // t%4
    const int lg   = lane >> 3;             // ldmatrix group 0..3
    const int lr   = lane & 7;              // ldmatrix row in group

    // ldmatrix per-lane byte offsets (within a plane/tile)
    const uint32_t aoff = ((wm + (lg & 1) * 8 + lr) * A_ROW_STRIDE + (lg >> 1) * 4) * 4;
    const uint32_t boff = ((wn + (lg >> 1) * 8 + lr) * A_ROW_STRIDE + (lg & 1) * 4) * 4;

    // ---- register-thin producer mappings ----
    const int ch    = tid & 3;
    const int arow0 = (tid >> 2) & 63;
    const int bt0   = tid >> 7;              // B plane (0=hi, 1=lo)
    const int bnr   = (tid >> 2) & 31;       // B n row

    const __nv_bfloat16* aP0 = Ahi + (size_t)(bm0 + arow0) * KP + ch * 8;   // plane hi
    const __nv_bfloat16* aP1 = Alo + (size_t)(bm0 + arow0) * KP + ch * 8;   // plane lo
    const __nv_bfloat16* bP  = (bt0 ? Blo : Bhi) + (size_t)(bn0 + bnr) * KP + ch * 8;

    const uint32_t aD = sbase + (arow0 * A_ROW_STRIDE + ch * 4) * 4;
    const uint32_t bD = sbase + (OFF_B_U32 + bt0 * B_TILE + bnr * A_ROW_STRIDE + ch * 4) * 4;

    #define CP_TILE(db)                                                          \
        do {                                                                     \
            cp16(aD + (db), aP0);                                                \
            cp16(aD + (db) + 64 * A_ROW_STRIDE * 4, aP0 + (size_t)64 * KP);      \
            cp16(aD + (db) + A_PLANE * 4, aP1);                                  \
            cp16(aD + (db) + A_PLANE * 4 + 64 * A_ROW_STRIDE * 4,                \
                 aP1 + (size_t)64 * KP);                                         \
            cp16(bD + (db) + 0 * 2 * B_TILE * 4, bP + (size_t)0 * HID * KP);     \
            cp16(bD + (db) + 1 * 2 * B_TILE * 4, bP + (size_t)1 * HID * KP);     \
            cp16(bD + (db) + 2 * 2 * B_TILE * 4, bP + (size_t)2 * HID * KP);     \
            cp16(bD + (db) + 3 * 2 * B_TILE * 4, bP + (size_t)3 * HID * KP);     \
        } while (0)

    float acc[4][2][2][4];                  // [op][mf][nf][c]
    #pragma unroll
    for (int o = 0; o < 4; o++)
        #pragma unroll
        for (int mf = 0; mf < 2; mf++)
            #pragma unroll
            for (int nf = 0; nf < 2; nf++)
                #pragma unroll
                for (int c = 0; c < 4; c++) acc[o][mf][nf][c] = 0.f;

    constexpr int nk = KP / BK;

    // prologue: fill buffer 0
    CP_TILE(0);
    cp_commit();
    cp_wait0();
    __syncthreads();

    #pragma unroll 1
    for (int kt = 0; kt < nk; kt++) {
        const int cur  = kt & 1;
        const bool more = (kt + 1 < nk);
        if (more) {
            aP0 += BK; aP1 += BK; bP += BK;
            CP_TILE((cur ^ 1) * BUF_BYTES);
            cp_commit();
        }

        const uint32_t bufA = sbase + cur * BUF_BYTES;
        const uint32_t bufB = bufA + OFF_B_U32 * 4;
        #pragma unroll
        for (int kp = 0; kp < 2; kp++) {
            uint32_t afr[2][2][4];    // [plane][mf][a0..a3]
            #pragma unroll
            for (int pl = 0; pl < 2; pl++)
                #pragma unroll
                for (int mf = 0; mf < 2; mf++)
                    ldmx4(afr[pl][mf],
                          bufA + pl * (A_PLANE * 4) + aoff + mf * (16 * A_ROW_STRIDE * 4) + kp * 32);
            #pragma unroll
            for (int op = 0; op < 4; op++) {
                uint32_t bfrg[2][4];  // [plane][nf0b0, nf0b1, nf1b0, nf1b1]
                #pragma unroll
                for (int pl = 0; pl < 2; pl++)
                    ldmx4(bfrg[pl],
                          bufB + (op * 2 + pl) * (B_TILE * 4) + boff + kp * 32);
                // term-ordered issue: all hi*hi, then hi*lo, then lo*hi —
                // accumulator reuse distance 4 independent HMMAs
                #pragma unroll
                for (int mf = 0; mf < 2; mf++)
                    #pragma unroll
                    for (int nf = 0; nf < 2; nf++)
                        mma16816(acc[op][mf][nf], afr[0][mf], bfrg[0][nf*2], bfrg[0][nf*2+1]);
                #pragma unroll
                for (int mf = 0; mf < 2; mf++)
                    #pragma unroll
                    for (int nf = 0; nf < 2; nf++)
                        mma16816(acc[op][mf][nf], afr[0][mf], bfrg[1][nf*2], bfrg[1][nf*2+1]);
                #pragma unroll
                for (int mf = 0; mf < 2; mf++)
                    #pragma unroll
                    for (int nf = 0; nf < 2; nf++)
                        mma16816(acc[op][mf][nf], afr[1][mf], bfrg[0][nf*2], bfrg[0][nf*2+1]);
            }
        }
        if (more) {
            cp_wait0();
            __syncthreads();
        }
    }
    #undef CP_TILE

    // ---- epilogue: bias + act + z-weighted op-sum, RMW into g_acc; when this
    //      stage finalizes node i == stage+1 (<=4), also emit bf16 split planes.
    const float z0 = zp[0], z1 = zp[1], z2 = zp[2], z3 = zp[3];
    const bool emit_split = (i == stage + 1) && (i <= 4);
    uint32_t* sp_hi = (uint32_t*)(g_a_hi + (size_t)(i - 1) * BATCH * HID);
    uint32_t* sp_lo = (uint32_t*)(g_a_lo + (size_t)(i - 1) * BATCH * HID);

    #pragma unroll
    for (int mf = 0; mf < 2; mf++)
        #pragma unroll
        for (int nf = 0; nf < 2; nf++) {
            const int n0 = bn0 + wn + nf * 8 + qk * 2;
            float bv[4][2];
            #pragma unroll
            for (int op = 0; op < 4; op++) {
                bv[op][0] = bias[op * HID + n0];
                bv[op][1] = bias[op * HID + n0 + 1];
            }
            #pragma unroll
            for (int half = 0; half < 2; half++) {
                const int m = bm0 + wm + mf * 16 + qr + half * 8;
                float r0 = 0.f, r1 = 0.f;
                #pragma unroll
                for (int op = 0; op < 4; op++) {
                    const float p0 = acc[op][mf][nf][half * 2 + 0] + bv[op][0];
                    const float p1 = acc[op][mf][nf][half * 2 + 1] + bv[op][1];
                    float a0, a1;
                    switch (op) {
                        case 0:  a0 = tanhf(p0);                      a1 = tanhf(p1);                      break;
                        case 1:  a0 = fmaxf(p0, 0.f);                 a1 = fmaxf(p1, 0.f);                 break;
                        case 2:  a0 = p0 > 0.f ? p0 : expm1f(p0);     a1 = p1 > 0.f ? p1 : expm1f(p1);     break;
                        default: a0 = p0 > 0.f ? p0 : 0.01f * p0;     a1 = p1 > 0.f ? p1 : 0.01f * p1;     break;
                    }
                    const float zv = (op == 0) ? z0 : (op == 1) ? z1 : (op == 2) ? z2 : z3;
                    r0 += zv * a0; r1 += zv * a1;
                }
                float* dst = accOut + (size_t)m * HID + n0;
                if (stage != 0) {
                    float2 old = *reinterpret_cast<const float2*>(dst);
                    r0 += old.x; r1 += old.y;
                }
                float2 res; res.x = r0; res.y = r1;
                *reinterpret_cast<float2*>(dst) = res;
                if (emit_split) {
                    __nv_bfloat16 h0, l0, h1, l1;
                    bf16split(r0, h0, l0);
                    bf16split(r1, h1, l1);
                    const size_t widx = ((size_t)m * HID + n0) >> 1;
                    sp_hi[widx] = packbf2(h0, h1);
                    sp_lo[widx] = packbf2(l0, l1);
                }
            }
        }
}

// ---------------------------------------------------------------------------
// out = tanh(acc5 @ Wout + bout)
// ---------------------------------------------------------------------------
__global__ void out_kernel(const float* __restrict__ Wout,
                           const float* __restrict__ bout,
                           float* __restrict__ out)
{
    const int gw   = (blockIdx.x * blockDim.x + threadIdx.x) >> 5;
    const int lane = threadIdx.x & 31;
    if (gw >= BATCH) return;
    const float* a = g_acc + (size_t)4 * BATCH * HID + (size_t)gw * HID;

    float s[NOUT];
    #pragma unroll
    for (int n = 0; n < NOUT; n++) s[n] = 0.f;
    for (int kk = lane; kk < HID; kk += 32) {
        const float av = a[kk];
        const float* wr = Wout + (size_t)kk * NOUT;
        #pragma unroll
        for (int n = 0; n < NOUT; n++) s[n] = fmaf(av, wr[n], s[n]);
    }
    #pragma unroll
    for (int off = 16; off; off >>= 1)
        #pragma unroll
        for (int n = 0; n < NOUT; n++)
            s[n] += __shfl_down_sync(0xffffffffu, s[n], off);
    if (lane == 0) {
        #pragma unroll
        for (int n = 0; n < NOUT; n++)
            out[(size_t)gw * NOUT + n] = tanhf(s[n] + bout[n]);
    }
}

// ---------------------------------------------------------------------------
extern "C" void kernel_launch(void* const* d_in, const int* in_sizes, int n_in,
                              void* d_out, int out_size)
{
    const float* x    = (const float*)d_in[0];
    const float* W0   = (const float*)d_in[1];
    const float* b0   = (const float*)d_in[2];
    const float* Wh   = (const float*)d_in[3];
    const float* bh   = (const float*)d_in[4];
    const float* Wout = (const float*)d_in[5];
    const float* bout = (const float*)d_in[6];
    const float* la   = (const float*)d_in[7];
    const float* eps  = (const float*)d_in[8];
    float* out = (float*)d_out;

    cudaFuncSetAttribute(stage_mma_kernel<KP0>,
                         cudaFuncAttributeMaxDynamicSharedMemorySize, SMEM_BYTES);
    cudaFuncSetAttribute(stage_mma_kernel<HID>,
                         cudaFuncAttributeMaxDynamicSharedMemorySize, SMEM_BYTES);

    z_kernel<<<1, 32>>>(la, eps);
    split_x_kernel<<<dim3(KP0 / 128, BATCH), 128>>>(x);
    split_t0_kernel<<<dim3(KP0 / 64, HID / 32, 20), dim3(32, 8)>>>(W0);
    split_th_kernel<<<dim3(HID / 64, HID / 32, 40), dim3(32, 8)>>>(Wh);
    for (int k = 0; k < 5; k++) {
        dim3 grid(BATCH / BM, HID / BN, 5 - k);
        if (k == 0)
            stage_mma_kernel<KP0><<<grid, NTHREADS, SMEM_BYTES>>>(k, b0, bh);
        else
            stage_mma_kernel<HID><<<grid, NTHREADS, SMEM_BYTES>>>(k, b0, bh);
    }
    out_kernel<<<(BATCH * 32) / 256, 256>>>(Wout, bout, out);
}